// round 1
// baseline (speedup 1.0000x reference)
#include <cuda_runtime.h>
#include <math_constants.h>

#define N_TOK 8192
#define DIM   256
#define BM    64
#define BN    32
#define NTHR  512

#define QS_STRIDE 260
#define KS_STRIDE 260
#define VS_STRIDE 512
#define PS_STRIDE 36

// Scratch for projected Q and K (fp32). 8 MB each.
__device__ float g_Q[N_TOK * DIM];
__device__ float g_K[N_TOK * DIM];

__device__ __forceinline__ void cp16(float* dst, const float* src) {
    unsigned d = (unsigned)__cvta_generic_to_shared(dst);
    asm volatile("cp.async.cg.shared.global [%0], [%1], 16;" :: "r"(d), "l"(src));
}
__device__ __forceinline__ void cp_wait_all() {
    asm volatile("cp.async.commit_group;");
    asm volatile("cp.async.wait_group 0;" ::: "memory");
}

// ---------------------------------------------------------------------------
// Projection: out[i][o] = sum_k X[i][k] * W[o][k]   (X:[N,D], W:[D,D] row=out)
// grid (N/64, D/64, 2): z=0 -> Q from img/Wq, z=1 -> K from text/Wk
// ---------------------------------------------------------------------------
__global__ __launch_bounds__(256) void proj_kernel(
    const float* __restrict__ img, const float* __restrict__ text,
    const float* __restrict__ Wq, const float* __restrict__ Wk)
{
    const float* X = blockIdx.z ? text : img;
    const float* W = blockIdx.z ? Wk : Wq;
    float* out = blockIdx.z ? g_K : g_Q;

    __shared__ float As[64][33];
    __shared__ float Bs[64][33];

    const int tx = threadIdx.x & 15;
    const int ty = threadIdx.x >> 4;
    const int row0 = blockIdx.x * 64;
    const int col0 = blockIdx.y * 64;

    float acc[4][4];
#pragma unroll
    for (int i = 0; i < 4; i++)
#pragma unroll
        for (int j = 0; j < 4; j++) acc[i][j] = 0.f;

    for (int k0 = 0; k0 < DIM; k0 += 32) {
        for (int e = threadIdx.x; e < 64 * 32; e += 256) {
            int r = e >> 5, k = e & 31;
            As[r][k] = X[(row0 + r) * DIM + k0 + k];
            Bs[r][k] = W[(col0 + r) * DIM + k0 + k];
        }
        __syncthreads();
#pragma unroll
        for (int k = 0; k < 32; k++) {
            float a0 = As[ty * 4 + 0][k], a1 = As[ty * 4 + 1][k];
            float a2 = As[ty * 4 + 2][k], a3 = As[ty * 4 + 3][k];
            float b0 = Bs[tx * 4 + 0][k], b1 = Bs[tx * 4 + 1][k];
            float b2 = Bs[tx * 4 + 2][k], b3 = Bs[tx * 4 + 3][k];
            acc[0][0] = fmaf(a0, b0, acc[0][0]); acc[0][1] = fmaf(a0, b1, acc[0][1]);
            acc[0][2] = fmaf(a0, b2, acc[0][2]); acc[0][3] = fmaf(a0, b3, acc[0][3]);
            acc[1][0] = fmaf(a1, b0, acc[1][0]); acc[1][1] = fmaf(a1, b1, acc[1][1]);
            acc[1][2] = fmaf(a1, b2, acc[1][2]); acc[1][3] = fmaf(a1, b3, acc[1][3]);
            acc[2][0] = fmaf(a2, b0, acc[2][0]); acc[2][1] = fmaf(a2, b1, acc[2][1]);
            acc[2][2] = fmaf(a2, b2, acc[2][2]); acc[2][3] = fmaf(a2, b3, acc[2][3]);
            acc[3][0] = fmaf(a3, b0, acc[3][0]); acc[3][1] = fmaf(a3, b1, acc[3][1]);
            acc[3][2] = fmaf(a3, b2, acc[3][2]); acc[3][3] = fmaf(a3, b3, acc[3][3]);
        }
        __syncthreads();
    }
#pragma unroll
    for (int i = 0; i < 4; i++) {
        float4 v = make_float4(acc[i][0], acc[i][1], acc[i][2], acc[i][3]);
        *(float4*)&out[(row0 + ty * 4 + i) * DIM + col0 + tx * 4] = v;
    }
}

// ---------------------------------------------------------------------------
// Flash attention: per CTA BM=64 query rows, loop over keys in BN=32 blocks.
// out_img = (softmax(QK^T)/16) @ img ; out_text likewise; V = [img | text].
// ---------------------------------------------------------------------------
__global__ __launch_bounds__(NTHR, 1) void attn_kernel(
    const float* __restrict__ img, const float* __restrict__ text,
    float* __restrict__ out)
{
    extern __shared__ float smf[];
    float* Qs   = smf;                       // BM x QS_STRIDE
    float* Ks   = Qs + BM * QS_STRIDE;       // BN x KS_STRIDE
    float* Vs   = Ks + BN * KS_STRIDE;       // BN x VS_STRIDE (img | text)
    float* Ps   = Vs + BN * VS_STRIDE;       // BM x PS_STRIDE
    float* m_s  = Ps + BM * PS_STRIDE;       // BM
    float* l_s  = m_s + BM;                  // BM
    float* sc_s = l_s + BM;                  // BM

    const int tid = threadIdx.x;
    const int qb = blockIdx.x * BM;

    // Load Q tile (64 x 256) via cp.async
#pragma unroll
    for (int w = 0; w < 8; w++) {
        int e = tid + w * NTHR;              // 0..4095 float4s
        int r = e >> 6, k4 = (e & 63) << 2;
        cp16(&Qs[r * QS_STRIDE + k4], &g_Q[(qb + r) * DIM + k4]);
    }
    if (tid < BM) { m_s[tid] = -CUDART_INF_F; l_s[tid] = 0.f; }
    cp_wait_all();
    __syncthreads();

    // S mapping: each thread: row sr, 4 cols {cg, cg+8, cg+16, cg+24}
    const int sr = tid >> 3, cg = tid & 7;
    // PV mapping: rows vty*4..+3, cols cx*16..+15
    const int vty = tid >> 5, cx = tid & 31;

    float4 acc[4][4];
#pragma unroll
    for (int i = 0; i < 4; i++)
#pragma unroll
        for (int q4 = 0; q4 < 4; q4++) acc[i][q4] = make_float4(0.f, 0.f, 0.f, 0.f);

    for (int kb = 0; kb < N_TOK; kb += BN) {
        // Fill K (32x256) and V (32x512 = img|text) via cp.async
#pragma unroll
        for (int w = 0; w < 4; w++) {
            int e = tid + w * NTHR;          // 0..2047
            int j = e >> 6, k4 = (e & 63) << 2;
            cp16(&Ks[j * KS_STRIDE + k4], &g_K[(kb + j) * DIM + k4]);
            cp16(&Vs[j * VS_STRIDE + k4], &img[(kb + j) * DIM + k4]);
            cp16(&Vs[j * VS_STRIDE + DIM + k4], &text[(kb + j) * DIM + k4]);
        }
        cp_wait_all();
        __syncthreads();

        // ---- S = Q K^T for this block (fp32) ----
        float s0 = 0.f, s1 = 0.f, s2 = 0.f, s3 = 0.f;
        const float* qp  = Qs + sr * QS_STRIDE;
        const float* kp0 = Ks + cg * KS_STRIDE;
        const float* kp1 = kp0 + 8 * KS_STRIDE;
        const float* kp2 = kp1 + 8 * KS_STRIDE;
        const float* kp3 = kp2 + 8 * KS_STRIDE;
#pragma unroll 8
        for (int k = 0; k < DIM; k += 4) {
            float4 q = *(const float4*)(qp + k);
            float4 a = *(const float4*)(kp0 + k);
            float4 b = *(const float4*)(kp1 + k);
            float4 c = *(const float4*)(kp2 + k);
            float4 d = *(const float4*)(kp3 + k);
            s0 = fmaf(q.x, a.x, s0); s0 = fmaf(q.y, a.y, s0);
            s0 = fmaf(q.z, a.z, s0); s0 = fmaf(q.w, a.w, s0);
            s1 = fmaf(q.x, b.x, s1); s1 = fmaf(q.y, b.y, s1);
            s1 = fmaf(q.z, b.z, s1); s1 = fmaf(q.w, b.w, s1);
            s2 = fmaf(q.x, c.x, s2); s2 = fmaf(q.y, c.y, s2);
            s2 = fmaf(q.z, c.z, s2); s2 = fmaf(q.w, c.w, s2);
            s3 = fmaf(q.x, d.x, s3); s3 = fmaf(q.y, d.y, s3);
            s3 = fmaf(q.z, d.z, s3); s3 = fmaf(q.w, d.w, s3);
        }

        // ---- online softmax (8-lane groups own one row) ----
        float mx = fmaxf(fmaxf(s0, s1), fmaxf(s2, s3));
        mx = fmaxf(mx, __shfl_xor_sync(0xffffffffu, mx, 1));
        mx = fmaxf(mx, __shfl_xor_sync(0xffffffffu, mx, 2));
        mx = fmaxf(mx, __shfl_xor_sync(0xffffffffu, mx, 4));
        float m_old = m_s[sr];
        float m_new = fmaxf(m_old, mx);
        float p0 = __expf(s0 - m_new);
        float p1 = __expf(s1 - m_new);
        float p2 = __expf(s2 - m_new);
        float p3 = __expf(s3 - m_new);
        float ls = p0 + p1 + p2 + p3;
        ls += __shfl_xor_sync(0xffffffffu, ls, 1);
        ls += __shfl_xor_sync(0xffffffffu, ls, 2);
        ls += __shfl_xor_sync(0xffffffffu, ls, 4);
        if (cg == 0) {
            float scale = __expf(m_old - m_new);   // 0 on first block (-inf)
            sc_s[sr] = scale;
            l_s[sr] = l_s[sr] * scale + ls;
            m_s[sr] = m_new;
        }
        Ps[sr * PS_STRIDE + cg     ] = p0;
        Ps[sr * PS_STRIDE + cg + 8 ] = p1;
        Ps[sr * PS_STRIDE + cg + 16] = p2;
        Ps[sr * PS_STRIDE + cg + 24] = p3;
        __syncthreads();

        // ---- rescale accumulators, then O += P @ V ----
        float scl[4];
#pragma unroll
        for (int i = 0; i < 4; i++) scl[i] = sc_s[vty * 4 + i];
#pragma unroll
        for (int i = 0; i < 4; i++)
#pragma unroll
            for (int q4 = 0; q4 < 4; q4++) {
                acc[i][q4].x *= scl[i]; acc[i][q4].y *= scl[i];
                acc[i][q4].z *= scl[i]; acc[i][q4].w *= scl[i];
            }

        const float* vp = Vs + cx * 16;
        const float* pp = Ps + (vty * 4) * PS_STRIDE;
#pragma unroll 4
        for (int j = 0; j < BN; j++) {
            float4 v0 = *(const float4*)(vp + j * VS_STRIDE + 0);
            float4 v1 = *(const float4*)(vp + j * VS_STRIDE + 4);
            float4 v2 = *(const float4*)(vp + j * VS_STRIDE + 8);
            float4 v3 = *(const float4*)(vp + j * VS_STRIDE + 12);
            float pr[4];
            pr[0] = pp[j];
            pr[1] = pp[PS_STRIDE + j];
            pr[2] = pp[2 * PS_STRIDE + j];
            pr[3] = pp[3 * PS_STRIDE + j];
#pragma unroll
            for (int i = 0; i < 4; i++) {
                acc[i][0].x = fmaf(pr[i], v0.x, acc[i][0].x);
                acc[i][0].y = fmaf(pr[i], v0.y, acc[i][0].y);
                acc[i][0].z = fmaf(pr[i], v0.z, acc[i][0].z);
                acc[i][0].w = fmaf(pr[i], v0.w, acc[i][0].w);
                acc[i][1].x = fmaf(pr[i], v1.x, acc[i][1].x);
                acc[i][1].y = fmaf(pr[i], v1.y, acc[i][1].y);
                acc[i][1].z = fmaf(pr[i], v1.z, acc[i][1].z);
                acc[i][1].w = fmaf(pr[i], v1.w, acc[i][1].w);
                acc[i][2].x = fmaf(pr[i], v2.x, acc[i][2].x);
                acc[i][2].y = fmaf(pr[i], v2.y, acc[i][2].y);
                acc[i][2].z = fmaf(pr[i], v2.z, acc[i][2].z);
                acc[i][2].w = fmaf(pr[i], v2.w, acc[i][2].w);
                acc[i][3].x = fmaf(pr[i], v3.x, acc[i][3].x);
                acc[i][3].y = fmaf(pr[i], v3.y, acc[i][3].y);
                acc[i][3].z = fmaf(pr[i], v3.z, acc[i][3].z);
                acc[i][3].w = fmaf(pr[i], v3.w, acc[i][3].w);
            }
        }
        __syncthreads();   // protect Ks/Vs/Ps before next iteration's fill
    }

    // ---- epilogue: out = acc / l * (1/sqrt(D)) ; split img/text halves ----
#pragma unroll
    for (int i = 0; i < 4; i++) {
        int row = qb + vty * 4 + i;
        float f = 0.0625f / l_s[vty * 4 + i];   // 1/sqrt(256) = 1/16
#pragma unroll
        for (int q4 = 0; q4 < 4; q4++) {
            int col = cx * 16 + q4 * 4;
            float4 o;
            o.x = acc[i][q4].x * f; o.y = acc[i][q4].y * f;
            o.z = acc[i][q4].z * f; o.w = acc[i][q4].w * f;
            float* dst = (col < DIM)
                       ? &out[row * DIM + col]
                       : &out[N_TOK * DIM + row * DIM + (col - DIM)];
            *(float4*)dst = o;
        }
    }
}

// ---------------------------------------------------------------------------
extern "C" void kernel_launch(void* const* d_in, const int* in_sizes, int n_in,
                              void* d_out, int out_size)
{
    const float* img  = (const float*)d_in[0];
    const float* text = (const float*)d_in[1];
    const float* Wq   = (const float*)d_in[2];
    const float* Wk   = (const float*)d_in[3];
    float* out = (float*)d_out;

    // Projections: Q = img @ Wq^T, K = text @ Wk^T
    dim3 pgrid(N_TOK / 64, DIM / 64, 2);
    proj_kernel<<<pgrid, 256>>>(img, text, Wq, Wk);

    // Flash attention
    size_t smem_bytes = (size_t)(BM * QS_STRIDE + BN * KS_STRIDE +
                                 BN * VS_STRIDE + BM * PS_STRIDE + 3 * BM) * sizeof(float);
    cudaFuncSetAttribute(attn_kernel, cudaFuncAttributeMaxDynamicSharedMemorySize,
                         (int)smem_bytes);
    attn_kernel<<<N_TOK / BM, NTHR, smem_bytes>>>(img, text, out);
}

// round 3
// speedup vs baseline: 5.3708x; 5.3708x over previous
#include <cuda_runtime.h>
#include <cuda_bf16.h>
#include <cstdint>

#define NT 8192
#define DM 256

// ============================ static device buffers ============================
__device__ __nv_bfloat16 g_Qhi[NT * DM], g_Qlo[NT * DM];     // Q' = img @ M (bf16 hi/lo)
__device__ __nv_bfloat16 g_Khi[NT * DM], g_Klo[NT * DM];     // text (bf16 hi/lo)
__device__ __nv_bfloat16 g_VThi[512 * NT], g_VTlo[512 * NT]; // V^T = [img|text]^T
__device__ __nv_bfloat16 g_Phi[(size_t)NT * NT];             // exp(S) hi
__device__ __nv_bfloat16 g_Plo[(size_t)NT * NT];             // exp(S) lo
__device__ float g_M[DM * DM];                               // Wq^T @ Wk
__device__ float g_rowsum[NT];

// ============================ PTX helpers ====================================
__device__ __forceinline__ uint32_t smem_u32(const void* p) {
    uint32_t a;
    asm("{ .reg .u64 t; cvta.to.shared.u64 t, %1; cvt.u32.u64 %0, t; }" : "=r"(a) : "l"(p));
    return a;
}
__device__ __forceinline__ void cpa16(uint32_t dst, const void* src) {
    asm volatile("cp.async.cg.shared.global [%0], [%1], 16;" :: "r"(dst), "l"(src));
}
__device__ __forceinline__ void ldm4(uint32_t* r, uint32_t addr) {
    asm volatile("ldmatrix.sync.aligned.m8n8.x4.shared.b16 {%0,%1,%2,%3}, [%4];"
        : "=r"(r[0]), "=r"(r[1]), "=r"(r[2]), "=r"(r[3]) : "r"(addr));
}
__device__ __forceinline__ void mma16816(float* c, const uint32_t* a, const uint32_t* b) {
    asm volatile("mma.sync.aligned.m16n8k16.row.col.f32.bf16.bf16.f32 "
        "{%0,%1,%2,%3}, {%4,%5,%6,%7}, {%8,%9}, {%0,%1,%2,%3};"
        : "+f"(c[0]), "+f"(c[1]), "+f"(c[2]), "+f"(c[3])
        : "r"(a[0]), "r"(a[1]), "r"(a[2]), "r"(a[3]), "r"(b[0]), "r"(b[1]));
}

// smem layout constants: 4 matrices [128 rows][40 bf16] (80B stride), 2 stages
#define SM_MAT   10240
#define SM_STAGE 40960

// ====================== shared HMMA mainloop (bf16x3) ========================
// A tiles rows M0..M0+127 of Ahi/Alo [*, LDA]; B tiles rows N0..N0+127 of Bhi/Blo.
// acc[mi][ni][4] accumulates C = Ahi*Bhi^T + Alo*Bhi^T + Ahi*Blo^T (fp32).
template<int NCH, int LDA>
__device__ __forceinline__ void mma_mainloop(
    const __nv_bfloat16* __restrict__ Ahi, const __nv_bfloat16* __restrict__ Alo,
    const __nv_bfloat16* __restrict__ Bhi, const __nv_bfloat16* __restrict__ Blo,
    int M0, int N0, uint32_t sm, float acc[4][4][4])
{
    const int tid = threadIdx.x, lane = tid & 31, wid = tid >> 5;
    const int wm = wid & 1, wn = wid >> 1;

    // per-thread ldmatrix base byte offsets within a matrix
    const uint32_t aRow = (uint32_t)((wm * 64 + (lane & 15)) * 80 + ((lane >> 4) << 4));
    const uint32_t bRow = (uint32_t)((wn * 32 + ((lane >> 4) << 3) + (lane & 7)) * 80
                                     + (((lane >> 3) & 1) << 4));

    // fill one stage: 4 matrices x 128 rows x 32 cols (8 cp16 per thread)
    auto fill = [&](int stage, int k0) {
        const uint32_t sb = sm + stage * SM_STAGE;
#pragma unroll
        for (int i = 0; i < 8; i++) {
            int e = tid + i * 256;
            int mat = e >> 9;                 // uniform per i
            int idx = e & 511;
            int r = idx >> 2, c = idx & 3;
            const __nv_bfloat16* base = (mat == 0) ? Ahi : (mat == 1) ? Alo
                                      : (mat == 2) ? Bhi : Blo;
            int row = (mat < 2) ? (M0 + r) : (N0 + r);
            cpa16(sb + mat * SM_MAT + r * 80 + c * 16,
                  base + (size_t)row * LDA + k0 + c * 8);
        }
        asm volatile("cp.async.commit_group;");
    };

    fill(0, 0);
#pragma unroll 1
    for (int ch = 0; ch < NCH; ch++) {
        if (ch + 1 < NCH) {
            fill((ch + 1) & 1, (ch + 1) * 32);
            asm volatile("cp.async.wait_group 1;" ::: "memory");
        } else {
            asm volatile("cp.async.wait_group 0;" ::: "memory");
        }
        __syncthreads();
        const uint32_t sb = sm + (ch & 1) * SM_STAGE;
#pragma unroll
        for (int ks = 0; ks < 2; ks++) {
            const uint32_t kOff = ks * 32;    // 16 bf16 = 32 bytes
            uint32_t ah[4][4], al[4][4], bh[2][4], bl[2][4];
#pragma unroll
            for (int mi = 0; mi < 4; mi++) {
                ldm4(ah[mi], sb + 0 * SM_MAT + aRow + mi * 1280 + kOff);
                ldm4(al[mi], sb + 1 * SM_MAT + aRow + mi * 1280 + kOff);
            }
#pragma unroll
            for (int nb = 0; nb < 2; nb++) {
                ldm4(bh[nb], sb + 2 * SM_MAT + bRow + nb * 1280 + kOff);
                ldm4(bl[nb], sb + 3 * SM_MAT + bRow + nb * 1280 + kOff);
            }
#pragma unroll
            for (int mi = 0; mi < 4; mi++)
#pragma unroll
                for (int ni = 0; ni < 4; ni++) {
                    const uint32_t* ph = &bh[ni >> 1][(ni & 1) * 2];
                    const uint32_t* pl = &bl[ni >> 1][(ni & 1) * 2];
                    mma16816(acc[mi][ni], ah[mi], ph);
                    mma16816(acc[mi][ni], al[mi], ph);
                    mma16816(acc[mi][ni], ah[mi], pl);
                }
        }
        __syncthreads();
    }
}

// ============================ small prep kernels ==============================

// M = Wq^T @ Wk
__global__ __launch_bounds__(256) void wmix_kernel(const float* __restrict__ Wq,
                                                   const float* __restrict__ Wk) {
    __shared__ float A[32][65], B[32][65];
    const int tx = threadIdx.x & 15, ty = threadIdx.x >> 4;
    const int f0 = blockIdx.x * 64, d0 = blockIdx.y * 64;
    float acc[4][4];
#pragma unroll
    for (int i = 0; i < 4; i++)
#pragma unroll
        for (int j = 0; j < 4; j++) acc[i][j] = 0.f;
    for (int e0 = 0; e0 < DM; e0 += 32) {
        for (int idx = threadIdx.x; idx < 32 * 64; idx += 256) {
            int e = idx >> 6, c = idx & 63;
            A[e][c] = Wq[(e0 + e) * DM + d0 + c];
            B[e][c] = Wk[(e0 + e) * DM + f0 + c];
        }
        __syncthreads();
#pragma unroll
        for (int e = 0; e < 32; e++) {
            float a0 = A[e][ty * 4], a1 = A[e][ty * 4 + 1], a2 = A[e][ty * 4 + 2], a3 = A[e][ty * 4 + 3];
            float b0 = B[e][tx * 4], b1 = B[e][tx * 4 + 1], b2 = B[e][tx * 4 + 2], b3 = B[e][tx * 4 + 3];
            acc[0][0] = fmaf(a0, b0, acc[0][0]); acc[0][1] = fmaf(a0, b1, acc[0][1]);
            acc[0][2] = fmaf(a0, b2, acc[0][2]); acc[0][3] = fmaf(a0, b3, acc[0][3]);
            acc[1][0] = fmaf(a1, b0, acc[1][0]); acc[1][1] = fmaf(a1, b1, acc[1][1]);
            acc[1][2] = fmaf(a1, b2, acc[1][2]); acc[1][3] = fmaf(a1, b3, acc[1][3]);
            acc[2][0] = fmaf(a2, b0, acc[2][0]); acc[2][1] = fmaf(a2, b1, acc[2][1]);
            acc[2][2] = fmaf(a2, b2, acc[2][2]); acc[2][3] = fmaf(a2, b3, acc[2][3]);
            acc[3][0] = fmaf(a3, b0, acc[3][0]); acc[3][1] = fmaf(a3, b1, acc[3][1]);
            acc[3][2] = fmaf(a3, b2, acc[3][2]); acc[3][3] = fmaf(a3, b3, acc[3][3]);
        }
        __syncthreads();
    }
#pragma unroll
    for (int i = 0; i < 4; i++)
#pragma unroll
        for (int j = 0; j < 4; j++)
            g_M[(d0 + ty * 4 + i) * DM + f0 + tx * 4 + j] = acc[i][j];
}

// Q' = img @ M -> bf16 hi/lo
__global__ __launch_bounds__(256) void projq_kernel(const float* __restrict__ img) {
    __shared__ float A[64][33], B[64][33];
    const int tx = threadIdx.x & 15, ty = threadIdx.x >> 4;
    const int row0 = blockIdx.x * 64, col0 = blockIdx.y * 64;
    float acc[4][4];
#pragma unroll
    for (int i = 0; i < 4; i++)
#pragma unroll
        for (int j = 0; j < 4; j++) acc[i][j] = 0.f;
    for (int k0 = 0; k0 < DM; k0 += 32) {
        for (int idx = threadIdx.x; idx < 64 * 32; idx += 256) {
            int r = idx >> 5, c = idx & 31;
            A[r][c] = img[(row0 + r) * DM + k0 + c];
            B[r][c] = g_M[(k0 + c) * DM + col0 + r];
        }
        __syncthreads();
#pragma unroll
        for (int k = 0; k < 32; k++) {
            float a0 = A[ty * 4][k], a1 = A[ty * 4 + 1][k], a2 = A[ty * 4 + 2][k], a3 = A[ty * 4 + 3][k];
            float b0 = B[tx * 4][k], b1 = B[tx * 4 + 1][k], b2 = B[tx * 4 + 2][k], b3 = B[tx * 4 + 3][k];
            acc[0][0] = fmaf(a0, b0, acc[0][0]); acc[0][1] = fmaf(a0, b1, acc[0][1]);
            acc[0][2] = fmaf(a0, b2, acc[0][2]); acc[0][3] = fmaf(a0, b3, acc[0][3]);
            acc[1][0] = fmaf(a1, b0, acc[1][0]); acc[1][1] = fmaf(a1, b1, acc[1][1]);
            acc[1][2] = fmaf(a1, b2, acc[1][2]); acc[1][3] = fmaf(a1, b3, acc[1][3]);
            acc[2][0] = fmaf(a2, b0, acc[2][0]); acc[2][1] = fmaf(a2, b1, acc[2][1]);
            acc[2][2] = fmaf(a2, b2, acc[2][2]); acc[2][3] = fmaf(a2, b3, acc[2][3]);
            acc[3][0] = fmaf(a3, b0, acc[3][0]); acc[3][1] = fmaf(a3, b1, acc[3][1]);
            acc[3][2] = fmaf(a3, b2, acc[3][2]); acc[3][3] = fmaf(a3, b3, acc[3][3]);
        }
        __syncthreads();
    }
#pragma unroll
    for (int i = 0; i < 4; i++)
#pragma unroll
        for (int j = 0; j < 4; j++) {
            float x = acc[i][j];
            __nv_bfloat16 h = __float2bfloat16(x);
            size_t o = (size_t)(row0 + ty * 4 + i) * DM + col0 + tx * 4 + j;
            g_Qhi[o] = h;
            g_Qlo[o] = __float2bfloat16(x - __bfloat162float(h));
        }
}

// text -> bf16 hi/lo (row-major)
__global__ __launch_bounds__(512) void conv_text_kernel(const float* __restrict__ text) {
    int i = blockIdx.x * 512 + threadIdx.x;
    if (i >= NT * DM / 4) return;
    float4 v = ((const float4*)text)[i];
    union { __nv_bfloat16 h[4]; uint2 u; } ph, pl;
    float x[4] = {v.x, v.y, v.z, v.w};
#pragma unroll
    for (int j = 0; j < 4; j++) {
        __nv_bfloat16 h = __float2bfloat16(x[j]);
        ph.h[j] = h;
        pl.h[j] = __float2bfloat16(x[j] - __bfloat162float(h));
    }
    ((uint2*)g_Khi)[i] = ph.u;
    ((uint2*)g_Klo)[i] = pl.u;
}

// V^T (512 x 8192) from [img|text]
__global__ __launch_bounds__(256) void conv_vt_kernel(const float* __restrict__ img,
                                                      const float* __restrict__ text) {
    __shared__ float t[32][33];
    const int k0 = blockIdx.x * 32, n0 = blockIdx.y * 32;
    const int tx = threadIdx.x & 31, ty = threadIdx.x >> 5;
    const float* src = (n0 < 256) ? img : text;
    const int nc = (n0 < 256) ? n0 : (n0 - 256);
    for (int i = ty; i < 32; i += 8)
        t[i][tx] = src[(size_t)(k0 + i) * DM + nc + tx];
    __syncthreads();
    for (int i = ty; i < 32; i += 8) {
        float v = t[tx][i];
        size_t o = (size_t)(n0 + i) * NT + k0 + tx;
        __nv_bfloat16 h = __float2bfloat16(v);
        g_VThi[o] = h;
        g_VTlo[o] = __float2bfloat16(v - __bfloat162float(h));
    }
}

__global__ void zero_sums_kernel() {
    int i = blockIdx.x * 1024 + threadIdx.x;
    if (i < NT) g_rowsum[i] = 0.f;
}

// ===================== GEMM 1: P = exp(Q' @ K^T), rowsums =====================
__global__ __launch_bounds__(256, 1) void gemm_qk_kernel() {
    extern __shared__ char dsm[];
    const uint32_t sm = (smem_u32(dsm) + 127u) & ~127u;
    const int M0 = blockIdx.y * 128, N0 = blockIdx.x * 128;

    float acc[4][4][4];
#pragma unroll
    for (int a = 0; a < 4; a++)
#pragma unroll
        for (int b = 0; b < 4; b++)
#pragma unroll
            for (int c = 0; c < 4; c++) acc[a][b][c] = 0.f;

    mma_mainloop<8, DM>(g_Qhi, g_Qlo, g_Khi, g_Klo, M0, N0, sm, acc);

    const int lane = threadIdx.x & 31, wid = threadIdx.x >> 5;
    const int wm = wid & 1, wn = wid >> 1;
#pragma unroll
    for (int mi = 0; mi < 4; mi++) {
        int r0 = M0 + wm * 64 + mi * 16 + (lane >> 2);
        int r1 = r0 + 8;
        float rs0 = 0.f, rs1 = 0.f;
#pragma unroll
        for (int ni = 0; ni < 4; ni++) {
            int gc = N0 + wn * 32 + ni * 8 + (lane & 3) * 2;
            float p0 = __expf(acc[mi][ni][0]);
            float p1 = __expf(acc[mi][ni][1]);
            float p2 = __expf(acc[mi][ni][2]);
            float p3 = __expf(acc[mi][ni][3]);
            rs0 += p0 + p1;
            rs1 += p2 + p3;
            __nv_bfloat16 h0 = __float2bfloat16(p0), h1 = __float2bfloat16(p1);
            __nv_bfloat16 h2 = __float2bfloat16(p2), h3 = __float2bfloat16(p3);
            union { __nv_bfloat16 h[2]; uint32_t u; } u01, u23, v01, v23;
            u01.h[0] = h0; u01.h[1] = h1;
            u23.h[0] = h2; u23.h[1] = h3;
            v01.h[0] = __float2bfloat16(p0 - __bfloat162float(h0));
            v01.h[1] = __float2bfloat16(p1 - __bfloat162float(h1));
            v23.h[0] = __float2bfloat16(p2 - __bfloat162float(h2));
            v23.h[1] = __float2bfloat16(p3 - __bfloat162float(h3));
            *(uint32_t*)(g_Phi + (size_t)r0 * NT + gc) = u01.u;
            *(uint32_t*)(g_Phi + (size_t)r1 * NT + gc) = u23.u;
            *(uint32_t*)(g_Plo + (size_t)r0 * NT + gc) = v01.u;
            *(uint32_t*)(g_Plo + (size_t)r1 * NT + gc) = v23.u;
        }
        rs0 += __shfl_xor_sync(0xffffffffu, rs0, 1);
        rs0 += __shfl_xor_sync(0xffffffffu, rs0, 2);
        rs1 += __shfl_xor_sync(0xffffffffu, rs1, 1);
        rs1 += __shfl_xor_sync(0xffffffffu, rs1, 2);
        if ((lane & 3) == 0) {
            atomicAdd(&g_rowsum[r0], rs0);
            atomicAdd(&g_rowsum[r1], rs1);
        }
    }
}

// ================= GEMM 2: out = (P @ V) / (16 * rowsum) ======================
__global__ __launch_bounds__(256, 1) void gemm_pv_kernel(float* __restrict__ out) {
    extern __shared__ char dsm[];
    const uint32_t sm = (smem_u32(dsm) + 127u) & ~127u;
    const int M0 = blockIdx.y * 128, N0 = blockIdx.x * 128;

    float acc[4][4][4];
#pragma unroll
    for (int a = 0; a < 4; a++)
#pragma unroll
        for (int b = 0; b < 4; b++)
#pragma unroll
            for (int c = 0; c < 4; c++) acc[a][b][c] = 0.f;

    mma_mainloop<NT / 32, NT>(g_Phi, g_Plo, g_VThi, g_VTlo, M0, N0, sm, acc);

    const int lane = threadIdx.x & 31, wid = threadIdx.x >> 5;
    const int wm = wid & 1, wn = wid >> 1;
#pragma unroll
    for (int mi = 0; mi < 4; mi++) {
        int r0 = M0 + wm * 64 + mi * 16 + (lane >> 2);
        int r1 = r0 + 8;
        float f0 = 0.0625f / g_rowsum[r0];
        float f1 = 0.0625f / g_rowsum[r1];
#pragma unroll
        for (int ni = 0; ni < 4; ni++) {
            int gc = N0 + wn * 32 + ni * 8 + (lane & 3) * 2;
            float* d0 = (gc < DM) ? (out + (size_t)r0 * DM + gc)
                                  : (out + (size_t)NT * DM + (size_t)r0 * DM + (gc - DM));
            float* d1 = (gc < DM) ? (out + (size_t)r1 * DM + gc)
                                  : (out + (size_t)NT * DM + (size_t)r1 * DM + (gc - DM));
            float2 w0 = make_float2(acc[mi][ni][0] * f0, acc[mi][ni][1] * f0);
            float2 w1 = make_float2(acc[mi][ni][2] * f1, acc[mi][ni][3] * f1);
            *(float2*)d0 = w0;
            *(float2*)d1 = w1;
        }
    }
}

// ============================ host launcher ===================================
extern "C" void kernel_launch(void* const* d_in, const int* in_sizes, int n_in,
                              void* d_out, int out_size)
{
    const float* img  = (const float*)d_in[0];
    const float* text = (const float*)d_in[1];
    const float* Wq   = (const float*)d_in[2];
    const float* Wk   = (const float*)d_in[3];
    float* out = (float*)d_out;

    const int GSM = 2 * SM_STAGE + 128;   // 82048 bytes
    static int attr_done = 0;
    if (!attr_done) {
        cudaFuncSetAttribute(gemm_qk_kernel, cudaFuncAttributeMaxDynamicSharedMemorySize, GSM);
        cudaFuncSetAttribute(gemm_pv_kernel, cudaFuncAttributeMaxDynamicSharedMemorySize, GSM);
        attr_done = 1;
    }

    wmix_kernel<<<dim3(4, 4), 256>>>(Wq, Wk);
    projq_kernel<<<dim3(128, 4), 256>>>(img);
    conv_text_kernel<<<(NT * DM / 4 + 511) / 512, 512>>>(text);
    conv_vt_kernel<<<dim3(256, 16), 256>>>(img, text);
    zero_sums_kernel<<<8, 1024>>>();
    gemm_qk_kernel<<<dim3(64, 64), 256, GSM>>>();
    gemm_pv_kernel<<<dim3(4, 64), 256, GSM>>>(out);
}

// round 6
// speedup vs baseline: 7.1890x; 1.3385x over previous
#include <cuda_runtime.h>
#include <cuda_bf16.h>
#include <cuda_fp16.h>
#include <cstdint>

#define NT 8192
#define DM 256
#define L2E 1.4426950408889634f

// ============================ static device buffers ============================
__device__ __nv_bfloat16 g_Qhi[NT * DM], g_Qlo[NT * DM];   // Q' = img @ M (bf16 hi/lo)
__device__ __nv_bfloat16 g_Khi[NT * DM], g_Klo[NT * DM];   // text (bf16 hi/lo)
__device__ __half g_VT[512 * NT];                          // V^T = [img|text]^T (fp16)
__device__ __half g_Shi[(size_t)NT * NT];                  // S hi (fp16)
__device__ __half g_Slo[(size_t)NT * NT];                  // S lo (fp16)
__device__ float g_M[DM * DM];                             // Wq^T @ Wk
__device__ int g_rowmax[NT];                               // float bits of (rowmax + 64)

// ============================ PTX helpers ====================================
__device__ __forceinline__ uint32_t smem_u32(const void* p) {
    uint32_t a;
    asm("{ .reg .u64 t; cvta.to.shared.u64 t, %1; cvt.u32.u64 %0, t; }" : "=r"(a) : "l"(p));
    return a;
}
__device__ __forceinline__ void cpa16(uint32_t dst, const void* src) {
    asm volatile("cp.async.cg.shared.global [%0], [%1], 16;" :: "r"(dst), "l"(src));
}
__device__ __forceinline__ void ldm4(uint32_t* r, uint32_t addr) {
    asm volatile("ldmatrix.sync.aligned.m8n8.x4.shared.b16 {%0,%1,%2,%3}, [%4];"
        : "=r"(r[0]), "=r"(r[1]), "=r"(r[2]), "=r"(r[3]) : "r"(addr));
}
__device__ __forceinline__ void mma16816(float* c, const uint32_t* a, const uint32_t* b) {
    asm volatile("mma.sync.aligned.m16n8k16.row.col.f32.bf16.bf16.f32 "
        "{%0,%1,%2,%3}, {%4,%5,%6,%7}, {%8,%9}, {%0,%1,%2,%3};"
        : "+f"(c[0]), "+f"(c[1]), "+f"(c[2]), "+f"(c[3])
        : "r"(a[0]), "r"(a[1]), "r"(a[2]), "r"(a[3]), "r"(b[0]), "r"(b[1]));
}
__device__ __forceinline__ void mma16816h(float* c, const uint32_t* a, const uint32_t* b) {
    asm volatile("mma.sync.aligned.m16n8k16.row.col.f32.f16.f16.f32 "
        "{%0,%1,%2,%3}, {%4,%5,%6,%7}, {%8,%9}, {%0,%1,%2,%3};"
        : "+f"(c[0]), "+f"(c[1]), "+f"(c[2]), "+f"(c[3])
        : "r"(a[0]), "r"(a[1]), "r"(a[2]), "r"(a[3]), "r"(b[0]), "r"(b[1]));
}
__device__ __forceinline__ float ex2f(float x) {
    float r;
    asm("ex2.approx.f32 %0, %1;" : "=f"(r) : "f"(x));
    return r;
}

// smem layout constants: matrices [rows][40 halfwords] (80B stride)
#define SM_MAT   10240          // 128 rows * 80B
#define SM_STAGE 40960

// ====================== GEMM1 HMMA mainloop (bf16x3) =========================
template<int NCH, int LDA>
__device__ __forceinline__ void mma_mainloop(
    const __nv_bfloat16* __restrict__ Ahi, const __nv_bfloat16* __restrict__ Alo,
    const __nv_bfloat16* __restrict__ Bhi, const __nv_bfloat16* __restrict__ Blo,
    int M0, int N0, uint32_t sm, float acc[4][4][4])
{
    const int tid = threadIdx.x, lane = tid & 31, wid = tid >> 5;
    const int wm = wid & 1, wn = wid >> 1;

    const uint32_t aRow = (uint32_t)((wm * 64 + (lane & 15)) * 80 + ((lane >> 4) << 4));
    const uint32_t bRow = (uint32_t)((wn * 32 + ((lane >> 4) << 3) + (lane & 7)) * 80
                                     + (((lane >> 3) & 1) << 4));

    auto fill = [&](int stage, int k0) {
        const uint32_t sb = sm + stage * SM_STAGE;
#pragma unroll
        for (int i = 0; i < 8; i++) {
            int e = tid + i * 256;
            int mat = e >> 9;
            int idx = e & 511;
            int r = idx >> 2, c = idx & 3;
            const __nv_bfloat16* base = (mat == 0) ? Ahi : (mat == 1) ? Alo
                                      : (mat == 2) ? Bhi : Blo;
            int row = (mat < 2) ? (M0 + r) : (N0 + r);
            cpa16(sb + mat * SM_MAT + r * 80 + c * 16,
                  base + (size_t)row * LDA + k0 + c * 8);
        }
        asm volatile("cp.async.commit_group;");
    };

    fill(0, 0);
#pragma unroll 1
    for (int ch = 0; ch < NCH; ch++) {
        if (ch + 1 < NCH) {
            fill((ch + 1) & 1, (ch + 1) * 32);
            asm volatile("cp.async.wait_group 1;" ::: "memory");
        } else {
            asm volatile("cp.async.wait_group 0;" ::: "memory");
        }
        __syncthreads();
        const uint32_t sb = sm + (ch & 1) * SM_STAGE;
#pragma unroll
        for (int ks = 0; ks < 2; ks++) {
            const uint32_t kOff = ks * 32;
            uint32_t ah[4][4], al[4][4], bh[2][4], bl[2][4];
#pragma unroll
            for (int mi = 0; mi < 4; mi++) {
                ldm4(ah[mi], sb + 0 * SM_MAT + aRow + mi * 1280 + kOff);
                ldm4(al[mi], sb + 1 * SM_MAT + aRow + mi * 1280 + kOff);
            }
#pragma unroll
            for (int nb = 0; nb < 2; nb++) {
                ldm4(bh[nb], sb + 2 * SM_MAT + bRow + nb * 1280 + kOff);
                ldm4(bl[nb], sb + 3 * SM_MAT + bRow + nb * 1280 + kOff);
            }
#pragma unroll
            for (int mi = 0; mi < 4; mi++)
#pragma unroll
                for (int ni = 0; ni < 4; ni++) {
                    const uint32_t* ph = &bh[ni >> 1][(ni & 1) * 2];
                    const uint32_t* pl = &bl[ni >> 1][(ni & 1) * 2];
                    mma16816(acc[mi][ni], ah[mi], ph);
                    mma16816(acc[mi][ni], al[mi], ph);
                    mma16816(acc[mi][ni], ah[mi], pl);
                }
        }
        __syncthreads();
    }
}

// ============================ small prep kernels ==============================

// M = Wq^T @ Wk
__global__ __launch_bounds__(256) void wmix_kernel(const float* __restrict__ Wq,
                                                   const float* __restrict__ Wk) {
    __shared__ float A[32][65], B[32][65];
    const int tx = threadIdx.x & 15, ty = threadIdx.x >> 4;
    const int f0 = blockIdx.x * 64, d0 = blockIdx.y * 64;
    float acc[4][4];
#pragma unroll
    for (int i = 0; i < 4; i++)
#pragma unroll
        for (int j = 0; j < 4; j++) acc[i][j] = 0.f;
    for (int e0 = 0; e0 < DM; e0 += 32) {
        for (int idx = threadIdx.x; idx < 32 * 64; idx += 256) {
            int e = idx >> 6, c = idx & 63;
            A[e][c] = Wq[(e0 + e) * DM + d0 + c];
            B[e][c] = Wk[(e0 + e) * DM + f0 + c];
        }
        __syncthreads();
#pragma unroll
        for (int e = 0; e < 32; e++) {
            float a0 = A[e][ty * 4], a1 = A[e][ty * 4 + 1], a2 = A[e][ty * 4 + 2], a3 = A[e][ty * 4 + 3];
            float b0 = B[e][tx * 4], b1 = B[e][tx * 4 + 1], b2 = B[e][tx * 4 + 2], b3 = B[e][tx * 4 + 3];
            acc[0][0] = fmaf(a0, b0, acc[0][0]); acc[0][1] = fmaf(a0, b1, acc[0][1]);
            acc[0][2] = fmaf(a0, b2, acc[0][2]); acc[0][3] = fmaf(a0, b3, acc[0][3]);
            acc[1][0] = fmaf(a1, b0, acc[1][0]); acc[1][1] = fmaf(a1, b1, acc[1][1]);
            acc[1][2] = fmaf(a1, b2, acc[1][2]); acc[1][3] = fmaf(a1, b3, acc[1][3]);
            acc[2][0] = fmaf(a2, b0, acc[2][0]); acc[2][1] = fmaf(a2, b1, acc[2][1]);
            acc[2][2] = fmaf(a2, b2, acc[2][2]); acc[2][3] = fmaf(a2, b3, acc[2][3]);
            acc[3][0] = fmaf(a3, b0, acc[3][0]); acc[3][1] = fmaf(a3, b1, acc[3][1]);
            acc[3][2] = fmaf(a3, b2, acc[3][2]); acc[3][3] = fmaf(a3, b3, acc[3][3]);
        }
        __syncthreads();
    }
#pragma unroll
    for (int i = 0; i < 4; i++)
#pragma unroll
        for (int j = 0; j < 4; j++)
            g_M[(d0 + ty * 4 + i) * DM + f0 + tx * 4 + j] = acc[i][j];
}

// Q' = img @ M -> bf16 hi/lo
__global__ __launch_bounds__(256) void projq_kernel(const float* __restrict__ img) {
    __shared__ float A[64][33], B[64][33];
    const int tx = threadIdx.x & 15, ty = threadIdx.x >> 4;
    const int row0 = blockIdx.x * 64, col0 = blockIdx.y * 64;
    float acc[4][4];
#pragma unroll
    for (int i = 0; i < 4; i++)
#pragma unroll
        for (int j = 0; j < 4; j++) acc[i][j] = 0.f;
    for (int k0 = 0; k0 < DM; k0 += 32) {
        for (int idx = threadIdx.x; idx < 64 * 32; idx += 256) {
            int r = idx >> 5, c = idx & 31;
            A[r][c] = img[(row0 + r) * DM + k0 + c];
            B[r][c] = g_M[(k0 + c) * DM + col0 + r];
        }
        __syncthreads();
#pragma unroll
        for (int k = 0; k < 32; k++) {
            float a0 = A[ty * 4][k], a1 = A[ty * 4 + 1][k], a2 = A[ty * 4 + 2][k], a3 = A[ty * 4 + 3][k];
            float b0 = B[tx * 4][k], b1 = B[tx * 4 + 1][k], b2 = B[tx * 4 + 2][k], b3 = B[tx * 4 + 3][k];
            acc[0][0] = fmaf(a0, b0, acc[0][0]); acc[0][1] = fmaf(a0, b1, acc[0][1]);
            acc[0][2] = fmaf(a0, b2, acc[0][2]); acc[0][3] = fmaf(a0, b3, acc[0][3]);
            acc[1][0] = fmaf(a1, b0, acc[1][0]); acc[1][1] = fmaf(a1, b1, acc[1][1]);
            acc[1][2] = fmaf(a1, b2, acc[1][2]); acc[1][3] = fmaf(a1, b3, acc[1][3]);
            acc[2][0] = fmaf(a2, b0, acc[2][0]); acc[2][1] = fmaf(a2, b1, acc[2][1]);
            acc[2][2] = fmaf(a2, b2, acc[2][2]); acc[2][3] = fmaf(a2, b3, acc[2][3]);
            acc[3][0] = fmaf(a3, b0, acc[3][0]); acc[3][1] = fmaf(a3, b1, acc[3][1]);
            acc[3][2] = fmaf(a3, b2, acc[3][2]); acc[3][3] = fmaf(a3, b3, acc[3][3]);
        }
        __syncthreads();
    }
#pragma unroll
    for (int i = 0; i < 4; i++)
#pragma unroll
        for (int j = 0; j < 4; j++) {
            float x = acc[i][j];
            __nv_bfloat16 h = __float2bfloat16(x);
            size_t o = (size_t)(row0 + ty * 4 + i) * DM + col0 + tx * 4 + j;
            g_Qhi[o] = h;
            g_Qlo[o] = __float2bfloat16(x - __bfloat162float(h));
        }
}

// text -> bf16 hi/lo (row-major)
__global__ __launch_bounds__(512) void conv_text_kernel(const float* __restrict__ text) {
    int i = blockIdx.x * 512 + threadIdx.x;
    if (i >= NT * DM / 4) return;
    float4 v = ((const float4*)text)[i];
    union { __nv_bfloat16 h[4]; uint2 u; } ph, pl;
    float x[4] = {v.x, v.y, v.z, v.w};
#pragma unroll
    for (int j = 0; j < 4; j++) {
        __nv_bfloat16 h = __float2bfloat16(x[j]);
        ph.h[j] = h;
        pl.h[j] = __float2bfloat16(x[j] - __bfloat162float(h));
    }
    ((uint2*)g_Khi)[i] = ph.u;
    ((uint2*)g_Klo)[i] = pl.u;
}

// V^T (512 x 8192) fp16 from [img|text]
__global__ __launch_bounds__(256) void conv_vt_kernel(const float* __restrict__ img,
                                                      const float* __restrict__ text) {
    __shared__ float t[32][33];
    const int k0 = blockIdx.x * 32, n0 = blockIdx.y * 32;
    const int tx = threadIdx.x & 31, ty = threadIdx.x >> 5;
    const float* src = (n0 < 256) ? img : text;
    const int nc = (n0 < 256) ? n0 : (n0 - 256);
    for (int i = ty; i < 32; i += 8)
        t[i][tx] = src[(size_t)(k0 + i) * DM + nc + tx];
    __syncthreads();
    for (int i = ty; i < 32; i += 8)
        g_VT[(size_t)(n0 + i) * NT + k0 + tx] = __float2half_rn(t[tx][i]);
}

__global__ void init_rowmax_kernel() {
    int i = blockIdx.x * 1024 + threadIdx.x;
    if (i < NT) g_rowmax[i] = 0;   // float 0.0 < s+64 always
}

// ============== GEMM 1: S = Q' @ K^T (bf16x3) -> fp16 hi/lo + rowmax =========
__global__ __launch_bounds__(256, 1) void gemm_qk_kernel() {
    extern __shared__ char dsm[];
    const uint32_t sm = (smem_u32(dsm) + 127u) & ~127u;
    const int M0 = blockIdx.y * 128, N0 = blockIdx.x * 128;

    float acc[4][4][4];
#pragma unroll
    for (int a = 0; a < 4; a++)
#pragma unroll
        for (int b = 0; b < 4; b++)
#pragma unroll
            for (int c = 0; c < 4; c++) acc[a][b][c] = 0.f;

    mma_mainloop<8, DM>(g_Qhi, g_Qlo, g_Khi, g_Klo, M0, N0, sm, acc);

    const int lane = threadIdx.x & 31, wid = threadIdx.x >> 5;
    const int wm = wid & 1, wn = wid >> 1;
#pragma unroll
    for (int mi = 0; mi < 4; mi++) {
        int r0 = M0 + wm * 64 + mi * 16 + (lane >> 2);
        int r1 = r0 + 8;
        float mx0 = -1e30f, mx1 = -1e30f;
#pragma unroll
        for (int ni = 0; ni < 4; ni++) {
            int gc = N0 + wn * 32 + ni * 8 + (lane & 3) * 2;
            float s0 = acc[mi][ni][0], s1 = acc[mi][ni][1];
            float s2 = acc[mi][ni][2], s3 = acc[mi][ni][3];
            mx0 = fmaxf(mx0, fmaxf(s0, s1));
            mx1 = fmaxf(mx1, fmaxf(s2, s3));
            __half h0 = __float2half_rn(s0), h1 = __float2half_rn(s1);
            __half h2 = __float2half_rn(s2), h3 = __float2half_rn(s3);
            union { __half h[2]; uint32_t u; } a01, a23, b01, b23;
            a01.h[0] = h0; a01.h[1] = h1;
            a23.h[0] = h2; a23.h[1] = h3;
            b01.h[0] = __float2half_rn(s0 - __half2float(h0));
            b01.h[1] = __float2half_rn(s1 - __half2float(h1));
            b23.h[0] = __float2half_rn(s2 - __half2float(h2));
            b23.h[1] = __float2half_rn(s3 - __half2float(h3));
            *(uint32_t*)(g_Shi + (size_t)r0 * NT + gc) = a01.u;
            *(uint32_t*)(g_Shi + (size_t)r1 * NT + gc) = a23.u;
            *(uint32_t*)(g_Slo + (size_t)r0 * NT + gc) = b01.u;
            *(uint32_t*)(g_Slo + (size_t)r1 * NT + gc) = b23.u;
        }
        mx0 = fmaxf(mx0, __shfl_xor_sync(0xffffffffu, mx0, 1));
        mx0 = fmaxf(mx0, __shfl_xor_sync(0xffffffffu, mx0, 2));
        mx1 = fmaxf(mx1, __shfl_xor_sync(0xffffffffu, mx1, 1));
        mx1 = fmaxf(mx1, __shfl_xor_sync(0xffffffffu, mx1, 2));
        if ((lane & 3) == 0) {
            atomicMax(&g_rowmax[r0], __float_as_int(mx0 + 64.f));
            atomicMax(&g_rowmax[r1], __float_as_int(mx1 + 64.f));
        }
    }
}

// ======= GEMM 2: out = (exp(S - max) @ V) / (16 * rowsum)   [fp16 x1] ========
// grid (2, 64); CTA tile 128m x 256n; 8 warps = 2m x 4n, warp 64x64.
// smem/stage: Shi 10240 | Slo 10240 | VT 20480  (40960); 2 stages.
__global__ __launch_bounds__(256, 1) void gemm_pv_kernel(float* __restrict__ out) {
    extern __shared__ char dsm[];
    const uint32_t sm = (smem_u32(dsm) + 127u) & ~127u;
    const int M0 = blockIdx.y * 128, N0 = blockIdx.x * 256;
    const int tid = threadIdx.x, lane = tid & 31, wid = tid >> 5;
    const int wm = wid & 1, wn = wid >> 1;

    const uint32_t aRow = (uint32_t)((wm * 64 + (lane & 15)) * 80 + ((lane >> 4) << 4));
    const uint32_t bRow = (uint32_t)((((lane >> 4) << 3) + (lane & 7)) * 80
                                     + (((lane >> 3) & 1) << 4)) + (uint32_t)(wn * 64 * 80);

    // per-row -max*log2e and rowsum accumulators
    float En[4][2], rs[4][2];
#pragma unroll
    for (int mi = 0; mi < 4; mi++) {
        int r0 = M0 + wm * 64 + mi * 16 + (lane >> 2);
        En[mi][0] = -(__int_as_float(g_rowmax[r0]) - 64.f) * L2E;
        En[mi][1] = -(__int_as_float(g_rowmax[r0 + 8]) - 64.f) * L2E;
        rs[mi][0] = 0.f;
        rs[mi][1] = 0.f;
    }

    float acc[4][8][4];
#pragma unroll
    for (int a = 0; a < 4; a++)
#pragma unroll
        for (int b = 0; b < 8; b++)
#pragma unroll
            for (int c = 0; c < 4; c++) acc[a][b][c] = 0.f;

    auto fill = [&](int stage, int k0) {
        const uint32_t sb = sm + stage * SM_STAGE;
#pragma unroll
        for (int i = 0; i < 4; i++) {           // A planes: Shi (i<2), Slo (i>=2)
            int e = tid + i * 256;
            int plane = i >> 1;
            int idx = e & 511;
            int r = idx >> 2, c = idx & 3;
            const __half* src = plane ? g_Slo : g_Shi;
            cpa16(sb + plane * SM_MAT + r * 80 + c * 16,
                  src + (size_t)(M0 + r) * NT + k0 + c * 8);
        }
#pragma unroll
        for (int i = 0; i < 4; i++) {           // B: VT 256 rows
            int idx = tid + i * 256;
            int r = idx >> 2, c = idx & 3;
            cpa16(sb + 2 * SM_MAT + r * 80 + c * 16,
                  g_VT + (size_t)(N0 + r) * NT + k0 + c * 8);
        }
        asm volatile("cp.async.commit_group;");
    };

    fill(0, 0);
#pragma unroll 1
    for (int ch = 0; ch < NT / 32; ch++) {
        if (ch + 1 < NT / 32) {
            fill((ch + 1) & 1, (ch + 1) * 32);
            asm volatile("cp.async.wait_group 1;" ::: "memory");
        } else {
            asm volatile("cp.async.wait_group 0;" ::: "memory");
        }
        __syncthreads();
        const uint32_t sb = sm + (ch & 1) * SM_STAGE;
#pragma unroll
        for (int ks = 0; ks < 2; ks++) {
            const uint32_t kOff = ks * 32;
            uint32_t af[4][4], bf[4][4];
#pragma unroll
            for (int mi = 0; mi < 4; mi++) {
                uint32_t sh[4], sl[4];
                ldm4(sh, sb + 0 * SM_MAT + aRow + mi * 1280 + kOff);
                ldm4(sl, sb + 1 * SM_MAT + aRow + mi * 1280 + kOff);
#pragma unroll
                for (int j = 0; j < 4; j++) {
                    float2 fh = __half22float2(*(__half2*)&sh[j]);
                    float2 fl = __half22float2(*(__half2*)&sl[j]);
                    float e = En[mi][j & 1];
                    float p0 = ex2f(fmaf(fh.x + fl.x, L2E, e));
                    float p1 = ex2f(fmaf(fh.y + fl.y, L2E, e));
                    rs[mi][j & 1] += p0 + p1;
                    __half2 hp = __floats2half2_rn(p0, p1);
                    af[mi][j] = *(uint32_t*)&hp;
                }
            }
#pragma unroll
            for (int nb = 0; nb < 4; nb++)
                ldm4(bf[nb], sb + 2 * SM_MAT + bRow + nb * 1280 + kOff);
#pragma unroll
            for (int mi = 0; mi < 4; mi++)
#pragma unroll
                for (int ni = 0; ni < 8; ni++)
                    mma16816h(acc[mi][ni], af[mi], &bf[ni >> 1][(ni & 1) * 2]);
        }
        __syncthreads();
    }

    // epilogue: normalize by warp-local rowsum (full k covered by this CTA)
#pragma unroll
    for (int mi = 0; mi < 4; mi++) {
        float l0 = rs[mi][0], l1 = rs[mi][1];
        l0 += __shfl_xor_sync(0xffffffffu, l0, 1);
        l0 += __shfl_xor_sync(0xffffffffu, l0, 2);
        l1 += __shfl_xor_sync(0xffffffffu, l1, 1);
        l1 += __shfl_xor_sync(0xffffffffu, l1, 2);
        float f0 = 0.0625f / l0, f1 = 0.0625f / l1;
        int r0 = M0 + wm * 64 + mi * 16 + (lane >> 2);
        int r1 = r0 + 8;
#pragma unroll
        for (int ni = 0; ni < 8; ni++) {
            int gc = N0 + wn * 64 + ni * 8 + (lane & 3) * 2;
            float* d0 = (gc < DM) ? (out + (size_t)r0 * DM + gc)
                                  : (out + (size_t)NT * DM + (size_t)r0 * DM + (gc - DM));
            float* d1 = (gc < DM) ? (out + (size_t)r1 * DM + gc)
                                  : (out + (size_t)NT * DM + (size_t)r1 * DM + (gc - DM));
            *(float2*)d0 = make_float2(acc[mi][ni][0] * f0, acc[mi][ni][1] * f0);
            *(float2*)d1 = make_float2(acc[mi][ni][2] * f1, acc[mi][ni][3] * f1);
        }
    }
}

// ============================ host launcher ===================================
extern "C" void kernel_launch(void* const* d_in, const int* in_sizes, int n_in,
                              void* d_out, int out_size)
{
    const float* img  = (const float*)d_in[0];
    const float* text = (const float*)d_in[1];
    const float* Wq   = (const float*)d_in[2];
    const float* Wk   = (const float*)d_in[3];
    float* out = (float*)d_out;

    const int GSM = 2 * SM_STAGE + 128;   // 82048 bytes
    static int attr_done = 0;
    if (!attr_done) {
        cudaFuncSetAttribute(gemm_qk_kernel, cudaFuncAttributeMaxDynamicSharedMemorySize, GSM);
        cudaFuncSetAttribute(gemm_pv_kernel, cudaFuncAttributeMaxDynamicSharedMemorySize, GSM);
        attr_done = 1;
    }

    wmix_kernel<<<dim3(4, 4), 256>>>(Wq, Wk);
    projq_kernel<<<dim3(128, 4), 256>>>(img);
    conv_text_kernel<<<(NT * DM / 4 + 511) / 512, 512>>>(text);
    conv_vt_kernel<<<dim3(256, 16), 256>>>(img, text);
    init_rowmax_kernel<<<8, 1024>>>();
    gemm_qk_kernel<<<dim3(64, 64), 256, GSM>>>();
    gemm_pv_kernel<<<dim3(2, 64), 256, GSM>>>(out);
}